// round 1
// baseline (speedup 1.0000x reference)
#include <cuda_runtime.h>

#define BB   4
#define CC   256
#define HH   56
#define NN   3136      // 56*56
#define NHD  8         // heads
#define HD   32        // head dim
#define NK   784       // reduced tokens (28*28)
#define PEW  111       // pos_emb width

// ---------------- scratch (device globals; no allocation) ----------------
__device__ float g_q  [BB*NHD*NN*HD];   // (b, head, n, d)
__device__ float g_k  [BB*NHD*NK*HD];   // (b, head, m, d)
__device__ float g_v  [BB*NHD*NK*HD];
__device__ float g_xkv[BB*NK*CC];       // (b, m, c)  pre/post LN
__device__ float g_ao [BB*NN*CC];       // (b, n, head*32+d)
__device__ float g_wt [1024*CC];        // transposed conv weight: [k][o]

// ---------------- 0: transpose sr_w (o,i,kh,kw) -> (k=i*4+p, o) ----------
__global__ void wt_kernel(const float* __restrict__ sr_w) {
    int k = blockIdx.x;           // 0..1023
    int o = threadIdx.x;          // 0..255
    g_wt[k*CC + o] = sr_w[o*1024 + k];
}

// ---------------- 1: Q projection  q[b,head,n,d] = sum_c x[b,c,n]Wq[c,hd] -
__global__ void gemm_q_kernel(const float* __restrict__ x,
                              const float* __restrict__ Wq) {
    __shared__ float As[16][68];
    __shared__ float Bs[16][64];
    int b  = blockIdx.z;
    int n0 = blockIdx.x * 64;
    int c0 = blockIdx.y * 64;
    int tid = threadIdx.x, tx = tid & 15, ty = tid >> 4;
    const float* xb = x + b*CC*NN;

    float acc[4][4];
#pragma unroll
    for (int i=0;i<4;i++)
#pragma unroll
        for (int j=0;j<4;j++) acc[i][j] = 0.f;

    for (int kt = 0; kt < 16; kt++) {
        int k0 = kt * 16;
#pragma unroll
        for (int u = 0; u < 4; u++) {
            int e = tid + 256*u; int k = e >> 6; int c = e & 63;
            As[k][c] = xb[(k0+k)*NN + n0 + c];
            Bs[k][c] = Wq[(k0+k)*CC + c0 + c];
        }
        __syncthreads();
#pragma unroll
        for (int kk = 0; kk < 16; kk++) {
            float a[4], bb[4];
#pragma unroll
            for (int j=0;j<4;j++) a[j]  = As[kk][tx*4+j];
#pragma unroll
            for (int i=0;i<4;i++) bb[i] = Bs[kk][ty*4+i];
#pragma unroll
            for (int i=0;i<4;i++)
#pragma unroll
                for (int j=0;j<4;j++) acc[i][j] = fmaf(bb[i], a[j], acc[i][j]);
        }
        __syncthreads();
    }
#pragma unroll
    for (int i=0;i<4;i++) {
        int cout = c0 + ty*4 + i;
        int head = cout >> 5, d = cout & 31;
        int base = ((b*NHD + head)*NN + n0 + tx*4)*HD + d;
#pragma unroll
        for (int j=0;j<4;j++) g_q[base + j*HD] = acc[i][j];
    }
}

// ---------------- 2: spatial-reduction conv as GEMM (K=1024) -------------
__global__ void gemm_conv_kernel(const float* __restrict__ x,
                                 const float* __restrict__ sr_b) {
    __shared__ float As[16][68];
    __shared__ float Bs[16][64];
    int b  = blockIdx.z;
    int m0 = blockIdx.x * 64;
    int o0 = blockIdx.y * 64;
    int tid = threadIdx.x, tx = tid & 15, ty = tid >> 4;
    const float* xb = x + b*CC*NN;

    // per-u row info (row = m, fixed across k-tiles)
    int kf[4], rl[4], sbase[4]; bool val[4];
#pragma unroll
    for (int u=0;u<4;u++) {
        int e = tid + 256*u;
        kf[u] = e >> 6; rl[u] = e & 63;
        int m = m0 + rl[u];
        val[u] = (m < NK);
        int mm = val[u] ? m : 0;
        int r = mm / 28, c = mm % 28;
        sbase[u] = (2*r)*HH + 2*c;
    }

    float acc[4][4];
#pragma unroll
    for (int i=0;i<4;i++)
#pragma unroll
        for (int j=0;j<4;j++) acc[i][j] = 0.f;

    for (int kt = 0; kt < 64; kt++) {
        int k0 = kt * 16;
#pragma unroll
        for (int u = 0; u < 4; u++) {
            int kg = k0 + kf[u];
            int ic = kg >> 2, kh = (kg >> 1) & 1, kw = kg & 1;
            As[kf[u]][rl[u]] = val[u] ? xb[ic*NN + sbase[u] + kh*HH + kw] : 0.f;
        }
#pragma unroll
        for (int u = 0; u < 4; u++) {
            int e = tid + 256*u; int k = e >> 6; int o = e & 63;
            Bs[k][o] = g_wt[(k0+k)*CC + o0 + o];
        }
        __syncthreads();
#pragma unroll
        for (int kk = 0; kk < 16; kk++) {
            float a[4], bb[4];
#pragma unroll
            for (int j=0;j<4;j++) a[j]  = As[kk][tx*4+j];
#pragma unroll
            for (int i=0;i<4;i++) bb[i] = Bs[kk][ty*4+i];
#pragma unroll
            for (int i=0;i<4;i++)
#pragma unroll
                for (int j=0;j<4;j++) acc[i][j] = fmaf(bb[i], a[j], acc[i][j]);
        }
        __syncthreads();
    }
#pragma unroll
    for (int j=0;j<4;j++) {
        int m = m0 + tx*4 + j;
        if (m < NK) {
            int row = b*NK + m;
#pragma unroll
            for (int i=0;i<4;i++) {
                int o = o0 + ty*4 + i;
                g_xkv[row*CC + o] = acc[i][j] + sr_b[o];
            }
        }
    }
}

// ---------------- 3: LayerNorm over C=256 per row -------------------------
__global__ void ln_kernel(const float* __restrict__ gamma,
                          const float* __restrict__ beta) {
    int row = blockIdx.x;          // 0..B*NK-1
    int t = threadIdx.x;           // 0..255
    float v = g_xkv[row*CC + t];
    float s = v, q = v*v;
#pragma unroll
    for (int m = 16; m >= 1; m >>= 1) {
        s += __shfl_xor_sync(0xffffffffu, s, m);
        q += __shfl_xor_sync(0xffffffffu, q, m);
    }
    __shared__ float r1[8], r2[8];
    if ((t & 31) == 0) { r1[t>>5] = s; r2[t>>5] = q; }
    __syncthreads();
    float tot = 0.f, tq = 0.f;
#pragma unroll
    for (int w = 0; w < 8; w++) { tot += r1[w]; tq += r2[w]; }
    float mean = tot * (1.f/256.f);
    float var  = tq * (1.f/256.f) - mean*mean;
    float inv  = rsqrtf(var + 1e-5f);
    g_xkv[row*CC + t] = (v - mean)*inv*gamma[t] + beta[t];
}

// ---------------- 4: KV projection, scatter into (b,head,m,d) -------------
// column c of the 512-wide output: c = d*16 + head*2 + s  (s: 0=k, 1=v)
__global__ void gemm_kv_kernel(const float* __restrict__ Wkv) {
    __shared__ float As[16][68];
    __shared__ float Bs[16][64];
    int b  = blockIdx.z;
    int m0 = blockIdx.x * 64;
    int c0 = blockIdx.y * 64;
    int tid = threadIdx.x, tx = tid & 15, ty = tid >> 4;

    int rl = tid >> 2;
    int kq = (tid & 3) * 4;
    int m  = m0 + rl;
    bool rvalid = (m < NK);

    float acc[4][4];
#pragma unroll
    for (int i=0;i<4;i++)
#pragma unroll
        for (int j=0;j<4;j++) acc[i][j] = 0.f;

    for (int kt = 0; kt < 16; kt++) {
        int k0 = kt * 16;
        float4 va = make_float4(0.f,0.f,0.f,0.f);
        if (rvalid)
            va = *reinterpret_cast<const float4*>(&g_xkv[(b*NK + m)*CC + k0 + kq]);
        As[kq+0][rl] = va.x; As[kq+1][rl] = va.y;
        As[kq+2][rl] = va.z; As[kq+3][rl] = va.w;
#pragma unroll
        for (int u = 0; u < 4; u++) {
            int e = tid + 256*u; int k = e >> 6; int c = e & 63;
            Bs[k][c] = Wkv[(k0+k)*512 + c0 + c];
        }
        __syncthreads();
#pragma unroll
        for (int kk = 0; kk < 16; kk++) {
            float a[4], bb[4];
#pragma unroll
            for (int j=0;j<4;j++) a[j]  = As[kk][tx*4+j];
#pragma unroll
            for (int i=0;i<4;i++) bb[i] = Bs[kk][ty*4+i];
#pragma unroll
            for (int i=0;i<4;i++)
#pragma unroll
                for (int j=0;j<4;j++) acc[i][j] = fmaf(bb[i], a[j], acc[i][j]);
        }
        __syncthreads();
    }
#pragma unroll
    for (int j=0;j<4;j++) {
        int mm = m0 + tx*4 + j;
        if (mm < NK) {
#pragma unroll
            for (int i=0;i<4;i++) {
                int c = c0 + ty*4 + i;
                int d = c >> 4, head = (c >> 1) & 7, s = c & 1;
                float* dst = s ? g_v : g_k;
                dst[((b*NHD + head)*NK + mm)*HD + d] = acc[i][j];
            }
        }
    }
}

// ---------------- 5: fused flash attention --------------------------------
// bias[n][m] = pos_emb[(ki-qi+55)*111 + (kj-qj+55)], ki=m/56, kj=m%56 (m<784)
__global__ void attn_kernel(const float* __restrict__ pos_emb) {
    __shared__ float qs[64][33];
    __shared__ float ks[64][33];
    __shared__ float vs[64][33];
    __shared__ float ps[64][65];

    int b = blockIdx.z, head = blockIdx.y, n0 = blockIdx.x * 64;
    int tid = threadIdx.x, tx = tid & 15, ty = tid >> 4;
    const float scale = 0.17677669529663687f;   // 32^-0.5

    const float* qbase = g_q + ((b*NHD + head)*NN + n0)*HD;
    const float* kbase = g_k + (b*NHD + head)*NK*HD;
    const float* vbase = g_v + (b*NHD + head)*NK*HD;

#pragma unroll
    for (int u = 0; u < 8; u++) {
        int e = tid + 256*u; int r = e >> 5; int d = e & 31;
        qs[r][d] = qbase[e] * scale;
    }

    int qi[4], qj[4];
#pragma unroll
    for (int i=0;i<4;i++) {
        int n = n0 + ty*4 + i;
        qi[i] = n / HH; qj[i] = n % HH;
    }

    float m_i[4], l_i[4], acc[4][2];
#pragma unroll
    for (int i=0;i<4;i++) { m_i[i] = -1e30f; l_i[i] = 0.f; acc[i][0]=0.f; acc[i][1]=0.f; }

    for (int kt = 0; kt < 13; kt++) {
        int mb = kt * 64;
        __syncthreads();
#pragma unroll
        for (int u = 0; u < 8; u++) {
            int e = tid + 256*u; int r = e >> 5; int d = e & 31;
            bool ok = (mb + r) < NK;
            ks[r][d] = ok ? kbase[mb*HD + e] : 0.f;
            vs[r][d] = ok ? vbase[mb*HD + e] : 0.f;
        }
        __syncthreads();

        float s[4][4];
#pragma unroll
        for (int i=0;i<4;i++)
#pragma unroll
            for (int j=0;j<4;j++) s[i][j] = 0.f;
#pragma unroll
        for (int dd = 0; dd < 32; dd++) {
            float a[4], bk[4];
#pragma unroll
            for (int i=0;i<4;i++) a[i]  = qs[ty*4+i][dd];
#pragma unroll
            for (int j=0;j<4;j++) bk[j] = ks[tx*4+j][dd];
#pragma unroll
            for (int i=0;i<4;i++)
#pragma unroll
                for (int j=0;j<4;j++) s[i][j] = fmaf(a[i], bk[j], s[i][j]);
        }
        // bias + mask
#pragma unroll
        for (int j=0;j<4;j++) {
            int mk = mb + tx*4 + j;
            bool okm = mk < NK;
            int ki = mk / HH, kj = mk % HH;
#pragma unroll
            for (int i=0;i<4;i++) {
                if (okm)
                    s[i][j] += __ldg(&pos_emb[(ki - qi[i] + 55)*PEW + (kj - qj[i] + 55)]);
                else
                    s[i][j] = -1e30f;
            }
        }
        // online softmax per row
#pragma unroll
        for (int i=0;i<4;i++) {
            float mx = fmaxf(fmaxf(s[i][0], s[i][1]), fmaxf(s[i][2], s[i][3]));
#pragma unroll
            for (int o = 8; o >= 1; o >>= 1)
                mx = fmaxf(mx, __shfl_xor_sync(0xffffffffu, mx, o));
            float mnew = fmaxf(m_i[i], mx);
            float f = __expf(m_i[i] - mnew);
            float rs = 0.f;
#pragma unroll
            for (int j=0;j<4;j++) {
                float p = __expf(s[i][j] - mnew);
                ps[ty*4+i][tx*4+j] = p;
                rs += p;
            }
#pragma unroll
            for (int o = 8; o >= 1; o >>= 1)
                rs += __shfl_xor_sync(0xffffffffu, rs, o);
            l_i[i] = l_i[i]*f + rs;
            acc[i][0] *= f; acc[i][1] *= f;
            m_i[i] = mnew;
        }
        __syncwarp();
        // O += P @ V
#pragma unroll 8
        for (int key = 0; key < 64; key++) {
            float v0 = vs[key][tx*2], v1 = vs[key][tx*2+1];
#pragma unroll
            for (int i=0;i<4;i++) {
                float p = ps[ty*4+i][key];
                acc[i][0] = fmaf(p, v0, acc[i][0]);
                acc[i][1] = fmaf(p, v1, acc[i][1]);
            }
        }
    }
#pragma unroll
    for (int i=0;i<4;i++) {
        int n = n0 + ty*4 + i;
        float inv = 1.f / l_i[i];
        int o = (b*NN + n)*CC + head*HD + tx*2;
        g_ao[o]   = acc[i][0] * inv;
        g_ao[o+1] = acc[i][1] * inv;
    }
}

// ---------------- 6: output projection + NCHW transpose -------------------
__global__ void gemm_proj_kernel(const float* __restrict__ pw,
                                 const float* __restrict__ pb,
                                 float* __restrict__ out) {
    __shared__ float As[16][68];
    __shared__ float Bs[16][64];
    int b  = blockIdx.z;
    int n0 = blockIdx.x * 64;
    int c0 = blockIdx.y * 64;
    int tid = threadIdx.x, tx = tid & 15, ty = tid >> 4;

    int rl = tid >> 2;
    int kq = (tid & 3) * 4;

    float acc[4][4];
#pragma unroll
    for (int i=0;i<4;i++)
#pragma unroll
        for (int j=0;j<4;j++) acc[i][j] = 0.f;

    for (int kt = 0; kt < 16; kt++) {
        int k0 = kt * 16;
        float4 va = *reinterpret_cast<const float4*>(&g_ao[(b*NN + n0 + rl)*CC + k0 + kq]);
        As[kq+0][rl] = va.x; As[kq+1][rl] = va.y;
        As[kq+2][rl] = va.z; As[kq+3][rl] = va.w;
#pragma unroll
        for (int u = 0; u < 4; u++) {
            int e = tid + 256*u; int k = e >> 6; int c = e & 63;
            Bs[k][c] = pw[(k0+k)*CC + c0 + c];
        }
        __syncthreads();
#pragma unroll
        for (int kk = 0; kk < 16; kk++) {
            float a[4], bb[4];
#pragma unroll
            for (int j=0;j<4;j++) a[j]  = As[kk][tx*4+j];
#pragma unroll
            for (int i=0;i<4;i++) bb[i] = Bs[kk][ty*4+i];
#pragma unroll
            for (int i=0;i<4;i++)
#pragma unroll
                for (int j=0;j<4;j++) acc[i][j] = fmaf(bb[i], a[j], acc[i][j]);
        }
        __syncthreads();
    }
#pragma unroll
    for (int i=0;i<4;i++) {
        int cout = c0 + ty*4 + i;
        float bias = pb[cout];
        float* o = out + (b*CC + cout)*NN + n0 + tx*4;
#pragma unroll
        for (int j=0;j<4;j++) o[j] = acc[i][j] + bias;
    }
}

// ---------------- launch ---------------------------------------------------
extern "C" void kernel_launch(void* const* d_in, const int* in_sizes, int n_in,
                              void* d_out, int out_size) {
    const float* x    = (const float*)d_in[0];
    const float* Wq   = (const float*)d_in[1];
    const float* Wkv  = (const float*)d_in[2];
    const float* sr_w = (const float*)d_in[3];
    const float* sr_b = (const float*)d_in[4];
    const float* ln_g = (const float*)d_in[5];
    const float* ln_b = (const float*)d_in[6];
    const float* pos  = (const float*)d_in[7];
    const float* pw   = (const float*)d_in[8];
    const float* pb   = (const float*)d_in[9];
    float* out = (float*)d_out;

    wt_kernel      <<<1024, 256>>>(sr_w);
    gemm_q_kernel  <<<dim3(49, 4, BB), 256>>>(x, Wq);
    gemm_conv_kernel<<<dim3(13, 4, BB), 256>>>(x, sr_b);
    ln_kernel      <<<BB*NK, 256>>>(ln_g, ln_b);
    gemm_kv_kernel <<<dim3(13, 8, BB), 256>>>(Wkv);
    attn_kernel    <<<dim3(49, 8, BB), 256>>>(pos);
    gemm_proj_kernel<<<dim3(49, 4, BB), 256>>>(pw, pb, out);
}